// round 1
// baseline (speedup 1.0000x reference)
#include <cuda_runtime.h>
#include <cuda_bf16.h>
#include <math.h>
#include <stdint.h>

// Problem constants (fixed by the dataset)
constexpr int cB  = 128;    // batch
constexpr int cT  = 16;     // t (new nodes per batch)
constexpr int cF  = 256;    // feature dim
constexpr int cN  = 1024;   // node buffer size
constexpr int cE  = 8192;   // edges per batch
constexpr int cNC = 256;    // compact node count (edge indices are in [0,256))

// Output layout (flattened tuple, float32): mx | new_nodes | edges | weights | T+taus
constexpr long OFF_MX = 0;
constexpr long OFF_NN = (long)cB * cT * cF;                 // 524288
constexpr long OFF_ED = OFF_NN + (long)cB * cN * cF;        // 34078720
constexpr long OFF_WT = OFF_ED + (long)cB * 2 * cE;         // 36175872
constexpr long OFF_TT = OFF_WT + (long)cB * cE;             // 37224448

// Scratch (__device__ globals — no allocation allowed)
__device__ float g_adj[(long)cB * cNC * cNC];   // dense per-batch adjacency (dst x src)
__device__ float g_SP [(long)cB * cNC * 512];   // [S | P] = H @ [Ws1 | Wm1]
__device__ float g_h1 [(long)cB * cNC * cF];    // layer-1 hidden, compact rows
__device__ float g_X  [(long)cB * cT * cF];     // gathered out-row inputs
__device__ float g_Hxe[(long)cB * cT * cF];     // tanh(X @ Ws1) (valid for rows >= 256)
__device__ float g_F  [(long)cB * cT * 512];    // [h1_row | agg2_row] for final GEMM
__device__ float g_W1 [cF * 512];               // [Ws1 | Wm1] packed along N
__device__ float g_W2 [512 * cF];               // [Ws2 ; Wm2] stacked along K

// ---------------------------------------------------------------------------
// tf32 helpers
// ---------------------------------------------------------------------------
__device__ __forceinline__ unsigned f2tf(float f) {
    unsigned u;
    asm("cvt.rna.tf32.f32 %0, %1;" : "=r"(u) : "f"(f));
    return u;
}

// ---------------------------------------------------------------------------
// Generic batched tf32 GEMM: D = [tanh]( A @ B [+ Cadd] )
// CTA tile 128x128, K-block 32, 8 warps (warp tile 64x32), mma.m16n8k8.tf32.
// All dims must be multiples of the tile (true for every call here).
// ---------------------------------------------------------------------------
__global__ __launch_bounds__(256) void gemm_tf32(
    const float* __restrict__ A,  long sA, int lda,
    const float* __restrict__ Bm, long sB, int ldb,
    const float* __restrict__ Cm, long sC, int ldc,   // may be null
    float* __restrict__ D,        long sD, int ldd,
    int K, int do_tanh)
{
    __shared__ float As[128 * 36];   // padded stride 36 -> conflict-free frag loads
    __shared__ float Bs[32 * 132];   // padded stride 132

    const int z = blockIdx.z;
    const float* Ab = A  + (long)z * sA;
    const float* Bb = Bm + (long)z * sB;
    const float* Cb = Cm ? (Cm + (long)z * sC) : nullptr;
    float*       Db = D  + (long)z * sD;

    const int gm = blockIdx.y * 128;
    const int gn = blockIdx.x * 128;
    const int tid  = threadIdx.x;
    const int warp = tid >> 5, lane = tid & 31;
    const int g = lane >> 2, tg = lane & 3;
    const int wm = (warp & 1) * 64;
    const int wn = (warp >> 1) * 32;

    float acc[4][4][4];
#pragma unroll
    for (int i = 0; i < 4; i++)
#pragma unroll
        for (int j = 0; j < 4; j++)
#pragma unroll
            for (int k2 = 0; k2 < 4; k2++) acc[i][j][k2] = 0.f;

    const int arow = tid >> 3, ac = (tid & 7) * 4;     // A tile: 128x32
    const int brow = tid >> 5, bc = (tid & 31) * 4;    // B tile: 32x128

    for (int kb = 0; kb < K; kb += 32) {
#pragma unroll
        for (int i = 0; i < 4; i++) {
            int r = arow + i * 32;
            float4 v = *reinterpret_cast<const float4*>(Ab + (long)(gm + r) * lda + kb + ac);
            float4 w;
            w.x = __uint_as_float(f2tf(v.x)); w.y = __uint_as_float(f2tf(v.y));
            w.z = __uint_as_float(f2tf(v.z)); w.w = __uint_as_float(f2tf(v.w));
            *reinterpret_cast<float4*>(&As[r * 36 + ac]) = w;
        }
#pragma unroll
        for (int i = 0; i < 4; i++) {
            int r = brow + i * 8;
            float4 v = *reinterpret_cast<const float4*>(Bb + (long)(kb + r) * ldb + gn + bc);
            float4 w;
            w.x = __uint_as_float(f2tf(v.x)); w.y = __uint_as_float(f2tf(v.y));
            w.z = __uint_as_float(f2tf(v.z)); w.w = __uint_as_float(f2tf(v.w));
            *reinterpret_cast<float4*>(&Bs[r * 132 + bc]) = w;
        }
        __syncthreads();

#pragma unroll
        for (int kk = 0; kk < 32; kk += 8) {
            unsigned a[4][4], b[4][2];
#pragma unroll
            for (int mi = 0; mi < 4; mi++) {
                int r0 = wm + mi * 16 + g;
                a[mi][0] = __float_as_uint(As[r0 * 36 + kk + tg]);
                a[mi][1] = __float_as_uint(As[(r0 + 8) * 36 + kk + tg]);
                a[mi][2] = __float_as_uint(As[r0 * 36 + kk + tg + 4]);
                a[mi][3] = __float_as_uint(As[(r0 + 8) * 36 + kk + tg + 4]);
            }
#pragma unroll
            for (int ni = 0; ni < 4; ni++) {
                int c0 = wn + ni * 8 + g;
                b[ni][0] = __float_as_uint(Bs[(kk + tg) * 132 + c0]);
                b[ni][1] = __float_as_uint(Bs[(kk + tg + 4) * 132 + c0]);
            }
#pragma unroll
            for (int mi = 0; mi < 4; mi++)
#pragma unroll
                for (int ni = 0; ni < 4; ni++)
                    asm volatile(
                        "mma.sync.aligned.m16n8k8.row.col.f32.tf32.tf32.f32 "
                        "{%0,%1,%2,%3}, {%4,%5,%6,%7}, {%8,%9}, {%0,%1,%2,%3};"
                        : "+f"(acc[mi][ni][0]), "+f"(acc[mi][ni][1]),
                          "+f"(acc[mi][ni][2]), "+f"(acc[mi][ni][3])
                        : "r"(a[mi][0]), "r"(a[mi][1]), "r"(a[mi][2]), "r"(a[mi][3]),
                          "r"(b[ni][0]), "r"(b[ni][1]));
        }
        __syncthreads();
    }

#pragma unroll
    for (int mi = 0; mi < 4; mi++) {
        int r0 = gm + wm + mi * 16 + g;
#pragma unroll
        for (int ni = 0; ni < 4; ni++) {
            int c0 = gn + wn + ni * 8 + tg * 2;
            float v00 = acc[mi][ni][0], v01 = acc[mi][ni][1];
            float v10 = acc[mi][ni][2], v11 = acc[mi][ni][3];
            if (Cb) {
                v00 += Cb[(long)r0 * ldc + c0];       v01 += Cb[(long)r0 * ldc + c0 + 1];
                v10 += Cb[(long)(r0 + 8) * ldc + c0]; v11 += Cb[(long)(r0 + 8) * ldc + c0 + 1];
            }
            if (do_tanh) { v00 = tanhf(v00); v01 = tanhf(v01); v10 = tanhf(v10); v11 = tanhf(v11); }
            Db[(long)r0 * ldd + c0]           = v00;
            Db[(long)r0 * ldd + c0 + 1]       = v01;
            Db[(long)(r0 + 8) * ldd + c0]     = v10;
            Db[(long)(r0 + 8) * ldd + c0 + 1] = v11;
        }
    }
}

// ---------------------------------------------------------------------------
// Elementwise / gather / scatter kernels
// ---------------------------------------------------------------------------
__global__ void k_zero4(float4* p, int n4) {
    for (int i = blockIdx.x * blockDim.x + threadIdx.x; i < n4; i += gridDim.x * blockDim.x) {
        p[i] = make_float4(0.f, 0.f, 0.f, 0.f);
    }
}

// new_nodes = nodes with rows [T[b], T[b]+16) replaced by x — written straight into d_out
__global__ void k_scatter(const float4* __restrict__ x, const float4* __restrict__ nodes,
                          const int* __restrict__ T, float4* __restrict__ out_nn) {
    const int total = cB * cN * (cF / 4);
    for (int idx = blockIdx.x * blockDim.x + threadIdx.x; idx < total; idx += gridDim.x * blockDim.x) {
        int b   = idx / (cN * 64);
        int rem = idx - b * (cN * 64);
        int n = rem >> 6, q = rem & 63;
        int d = n - T[b];
        float4 v = (d >= 0 && d < cT) ? x[((long)b * cT + d) * 64 + q] : nodes[idx];
        out_nn[idx] = v;
    }
}

__global__ void k_edges_cast(const int* __restrict__ e, float* __restrict__ o) {
    const int total = cB * 2 * cE;
    for (int i = blockIdx.x * blockDim.x + threadIdx.x; i < total; i += gridDim.x * blockDim.x)
        o[i] = (float)e[i];
}

__global__ void k_copy4(const float4* __restrict__ s, float4* __restrict__ d, int n4) {
    for (int i = blockIdx.x * blockDim.x + threadIdx.x; i < n4; i += gridDim.x * blockDim.x)
        d[i] = s[i];
}

__global__ void k_tt(const int* __restrict__ T, const int* __restrict__ taus, float* __restrict__ o) {
    int i = threadIdx.x;
    if (i < cB) o[i] = (float)(T[i] + taus[i]);
}

__global__ void k_adj_build(const int* __restrict__ edges, const float* __restrict__ w) {
    const int total = cB * cE;
    for (int i = blockIdx.x * blockDim.x + threadIdx.x; i < total; i += gridDim.x * blockDim.x) {
        int b = i / cE, e = i - b * cE;
        int s = edges[(long)b * 2 * cE + e];
        int d = edges[(long)b * 2 * cE + cE + e];
        if (s >= 0 && d >= 0 && s < cNC && d < cNC) {
            atomicAdd(&g_adj[((long)b * cNC + d) * cNC + s], w[(long)b * cE + e]);
        }
    }
}

__global__ void k_packW(const float* __restrict__ Ws1, const float* __restrict__ Wm1,
                        const float* __restrict__ Ws2, const float* __restrict__ Wm2) {
    int i = blockIdx.x * blockDim.x + threadIdx.x;
    if (i < cF * cF) {
        int k = i >> 8, n = i & 255;
        g_W1[k * 512 + n]       = Ws1[i];
        g_W1[k * 512 + 256 + n] = Wm1[i];
        g_W2[i]                 = Ws2[i];   // K rows 0..255
        g_W2[cF * cF + i]       = Wm2[i];   // K rows 256..511
    }
}

// gather out-row node features (post-scatter) into g_X
__global__ void k_gatherX(const float4* __restrict__ out_nn, const int* __restrict__ T) {
    const int total = cB * cT * 64;
    for (int idx = blockIdx.x * blockDim.x + threadIdx.x; idx < total; idx += gridDim.x * blockDim.x) {
        int j = idx >> 6, q = idx & 63;
        int b = j / cT, i = j - b * cT;
        int row = T[b] + i;
        reinterpret_cast<float4*>(g_X)[idx] = out_nn[((long)b * cN + row) * 64 + q];
    }
}

// agg2 rows (Adj[row,:] @ h1) + pack [h1_row | agg2_row] into g_F. One CTA per batch.
__global__ __launch_bounds__(256) void k_aggpack(const int* __restrict__ T) {
    __shared__ float adj_sm[cT][cNC];
    const int b = blockIdx.x;
    const int c = threadIdx.x;     // 256 threads = 256 feature columns
    const int Tb = T[b];

#pragma unroll
    for (int r = 0; r < cT; r++) {
        int row = Tb + r;
        adj_sm[r][c] = (row < cNC) ? g_adj[((long)b * cNC + row) * cNC + c] : 0.f;
    }
    __syncthreads();

    float acc[cT];
#pragma unroll
    for (int r = 0; r < cT; r++) acc[r] = 0.f;

    const float* h1b = g_h1 + (long)b * cNC * cF;
#pragma unroll 4
    for (int s = 0; s < cNC; s++) {
        float v = h1b[s * cF + c];
#pragma unroll
        for (int r = 0; r < cT; r++) acc[r] += adj_sm[r][s] * v;
    }

#pragma unroll
    for (int r = 0; r < cT; r++) {
        int row = Tb + r;
        long j = (long)b * cT + r;
        g_F[j * 512 + 256 + c] = acc[r];   // agg2 (zero automatically if row >= 256)
        g_F[j * 512 + c] = (row < cNC) ? g_h1[((long)b * cNC + row) * cF + c]
                                       : g_Hxe[j * cF + c];
    }
}

// ---------------------------------------------------------------------------
// Launcher
// ---------------------------------------------------------------------------
extern "C" void kernel_launch(void* const* d_in, const int* in_sizes, int n_in,
                              void* d_out, int out_size) {
    const float* x       = (const float*)d_in[0];
    const int*   taus    = (const int*)  d_in[1];
    const float* nodes   = (const float*)d_in[2];
    const int*   edges   = (const int*)  d_in[3];
    const float* weights = (const float*)d_in[4];
    const int*   T       = (const int*)  d_in[5];
    const float* Ws1     = (const float*)d_in[6];
    const float* Wm1     = (const float*)d_in[7];
    const float* Ws2     = (const float*)d_in[8];
    const float* Wm2     = (const float*)d_in[9];

    float* out    = (float*)d_out;
    float* out_mx = out + OFF_MX;
    float* out_nn = out + OFF_NN;
    float* out_ed = out + OFF_ED;
    float* out_wt = out + OFF_WT;
    float* out_tt = out + OFF_TT;

    // device addresses of scratch symbols (host-side pointer values for kernel args)
    float *p_adj, *p_SP, *p_h1, *p_X, *p_F, *p_Hxe, *p_W1, *p_W2;
    cudaGetSymbolAddress((void**)&p_adj, g_adj);
    cudaGetSymbolAddress((void**)&p_SP,  g_SP);
    cudaGetSymbolAddress((void**)&p_h1,  g_h1);
    cudaGetSymbolAddress((void**)&p_X,   g_X);
    cudaGetSymbolAddress((void**)&p_F,   g_F);
    cudaGetSymbolAddress((void**)&p_Hxe, g_Hxe);
    cudaGetSymbolAddress((void**)&p_W1,  g_W1);
    cudaGetSymbolAddress((void**)&p_W2,  g_W2);

    // 1) zero adjacency
    k_zero4<<<2048, 256>>>((float4*)p_adj, cB * cNC * cNC / 4);

    // 2) passthrough outputs
    k_scatter<<<4096, 256>>>((const float4*)x, (const float4*)nodes, T, (float4*)out_nn);
    k_edges_cast<<<4096, 256>>>(edges, out_ed);
    k_copy4<<<1024, 256>>>((const float4*)weights, (float4*)out_wt, cB * cE / 4);
    k_tt<<<1, 128>>>(T, taus, out_tt);

    // 3) build adjacency + pack weights
    k_adj_build<<<4096, 256>>>(edges, weights);
    k_packW<<<256, 256>>>(Ws1, Wm1, Ws2, Wm2);

    // 4) GEMM1: [S|P] = NN_compact @ [Ws1|Wm1]   (batched: M=256, N=512, K=256)
    gemm_tf32<<<dim3(4, 2, cB), 256>>>(
        out_nn, (long)cN * cF, cF,
        p_W1,   0,             512,
        nullptr, 0, 0,
        p_SP,   (long)cNC * 512, 512,
        cF, 0);

    // 5) GEMM2: h1 = tanh(S + Adj @ P)   (batched: M=N=K=256)
    gemm_tf32<<<dim3(2, 2, cB), 256>>>(
        p_adj,     (long)cNC * cNC, cNC,
        p_SP + 256, (long)cNC * 512, 512,
        p_SP,      (long)cNC * 512, 512,
        p_h1,      (long)cNC * cF,  cF,
        cNC, 1);

    // 6) gather out-row inputs, layer-1 for rows >= 256 (agg = 0)
    k_gatherX<<<512, 256>>>((const float4*)out_nn, T);
    gemm_tf32<<<dim3(2, 16, 1), 256>>>(
        p_X, 0, cF,
        Ws1, 0, cF,
        nullptr, 0, 0,
        p_Hxe, 0, cF,
        cF, 1);

    // 7) agg2 rows + pack [h1_row | agg2_row]
    k_aggpack<<<cB, 256>>>(T);

    // 8) final GEMM: mx = tanh(F @ [Ws2;Wm2])   (M=2048, K=512, N=256)
    gemm_tf32<<<dim3(2, 16, 1), 256>>>(
        p_F, 0, 512,
        p_W2, 0, cF,
        nullptr, 0, 0,
        out_mx, 0, cF,
        512, 1);
}

// round 2
// speedup vs baseline: 1.3350x; 1.3350x over previous
#include <cuda_runtime.h>
#include <cuda_fp16.h>
#include <math.h>
#include <stdint.h>

// Problem constants (fixed by the dataset)
constexpr int cB  = 128;
constexpr int cT  = 16;
constexpr int cF  = 256;
constexpr int cN  = 1024;
constexpr int cE  = 8192;
constexpr int cNC = 256;               // edge indices live in [0,256)
constexpr int M1   = cB * cNC;         // 32768 compact rows
constexpr int MX   = cB * cT;          // 2048 output rows
constexpr int MEXT = M1 + MX;          // 34816

// Output layout (flattened tuple, float32): mx | new_nodes | edges | weights | T+taus
constexpr long OFF_MX = 0;
constexpr long OFF_NN = (long)cB * cT * cF;
constexpr long OFF_ED = OFF_NN + (long)cB * cN * cF;
constexpr long OFF_WT = OFF_ED + (long)cB * 2 * cE;
constexpr long OFF_TT = OFF_WT + (long)cB * cE;

// Scratch (__device__ globals — no allocation allowed)
__device__ float  g_adj [(long)cB * cNC * cNC];   // fp32 adjacency (atomic build)
__device__ __half g_adjh[(long)cB * cNC * cNC];   // half copy for MMA
__device__ __half g_H  [(long)MEXT * cF];         // [compact nodes | X rows], half
__device__ __half g_HT [(long)cB * cNC * cF];     // per-batch transposed H [feat][node]
__device__ __half g_AH [(long)MEXT * cF];         // Adj@H (tail rows = 0)
__device__ __half g_h1 [(long)MEXT * cF];         // layer-1 hidden
__device__ __half g_F1 [(long)MX * cF];           // gathered h1 rows for layer-2 self term
__device__ __half g_ag2[(long)MX * cF];           // layer-2 aggregation rows
__device__ __half g_WT [4][cF * cF];              // Ws1^T, Wm1^T, Ws2^T, Wm2^T (half)

// ---------------------------------------------------------------------------
// helpers
// ---------------------------------------------------------------------------
__device__ __forceinline__ void cpa16(void* s, const void* g) {
    unsigned sa = (unsigned)__cvta_generic_to_shared(s);
    asm volatile("cp.async.cg.shared.global [%0], [%1], 16;" :: "r"(sa), "l"(g));
}
__device__ __forceinline__ float fast_tanh(float x) {
    // tanh(x) = sign(x) * (1 - 2/(exp(2|x|)+1));  ex2/rcp approx err ~1e-6
    float ax = fabsf(x);
    float e;
    asm("ex2.approx.f32 %0, %1;" : "=f"(e) : "f"(ax * 2.8853900817779268f)); // 2*log2(e)
    float t = 1.0f - __fdividef(2.0f, e + 1.0f);
    return copysignf(t, x);
}

// ---------------------------------------------------------------------------
// fp16 pipelined GEMM: D = [tanh]( A1@B1t [+ A2@B2t] )
// A row-major [M][256] per segment; B given TRANSPOSED: [N][256] row-major.
// CTA tile 128x128, K-block 32, cp.async double buffer, mma.m16n8k16.
// ---------------------------------------------------------------------------
__global__ __launch_bounds__(256, 1) void hgemm(
    const __half* __restrict__ A1, long sA,
    const __half* __restrict__ B1, long sB,
    const __half* __restrict__ A2, const __half* __restrict__ B2,
    void* __restrict__ Dp, long sD,
    int nseg, int out_half, int do_tanh)
{
    __shared__ alignas(16) __half As[2][128 * 40];
    __shared__ alignas(16) __half Bs[2][128 * 40];

    const int z = blockIdx.z;
    const __half* Ab[2]; Ab[0] = A1 + (long)z * sA; Ab[1] = A2 ? A2 + (long)z * sA : Ab[0];
    const __half* Bb[2]; Bb[0] = B1 + (long)z * sB; Bb[1] = B2 ? B2 : Bb[0];

    const long gm = (long)blockIdx.y * 128;
    const long gn = (long)blockIdx.x * 128;
    const int tid = threadIdx.x, warp = tid >> 5, lane = tid & 31;
    const int g = lane >> 2, tg = lane & 3;
    const int wm = (warp & 1) * 64, wn = (warp >> 1) * 32;
    const int nkb = nseg * 8;

    const int lrow = tid >> 1;             // smem load row (0..127)
    const int lcol = (tid & 1) * 16;       // half offset within 32-wide k-block

    float acc[4][4][4];
#pragma unroll
    for (int a = 0; a < 4; a++)
#pragma unroll
        for (int b = 0; b < 4; b++)
#pragma unroll
            for (int c = 0; c < 4; c++) acc[a][b][c] = 0.f;

#define LOADK(KB, BUF) do {                                                     \
    int seg_ = (KB) >> 3, kk_ = ((KB) & 7) * 32;                                \
    const __half* Ag_ = Ab[seg_] + (gm + lrow) * 256 + kk_ + lcol;              \
    const __half* Bg_ = Bb[seg_] + (gn + lrow) * 256 + kk_ + lcol;              \
    __half* Asd_ = &As[BUF][lrow * 40 + lcol];                                  \
    __half* Bsd_ = &Bs[BUF][lrow * 40 + lcol];                                  \
    cpa16(Asd_, Ag_); cpa16(Asd_ + 8, Ag_ + 8);                                 \
    cpa16(Bsd_, Bg_); cpa16(Bsd_ + 8, Bg_ + 8);                                 \
    asm volatile("cp.async.commit_group;");                                     \
} while (0)

    LOADK(0, 0);
    for (int kb = 0; kb < nkb; kb++) {
        asm volatile("cp.async.wait_group 0;" ::: "memory");
        __syncthreads();
        if (kb + 1 < nkb) LOADK(kb + 1, (kb + 1) & 1);

        const unsigned* As2 = (const unsigned*)As[kb & 1];
        const unsigned* Bs2 = (const unsigned*)Bs[kb & 1];
#pragma unroll
        for (int ks = 0; ks < 2; ks++) {
            const int kc = ks * 8 + tg;           // half2 column
            unsigned af[4][4], bf[4][2];
#pragma unroll
            for (int mi = 0; mi < 4; mi++) {
                int r = wm + mi * 16 + g;
                af[mi][0] = As2[r * 20 + kc];
                af[mi][1] = As2[(r + 8) * 20 + kc];
                af[mi][2] = As2[r * 20 + kc + 4];
                af[mi][3] = As2[(r + 8) * 20 + kc + 4];
            }
#pragma unroll
            for (int ni = 0; ni < 4; ni++) {
                int n = wn + ni * 8 + g;
                bf[ni][0] = Bs2[n * 20 + kc];
                bf[ni][1] = Bs2[n * 20 + kc + 4];
            }
#pragma unroll
            for (int mi = 0; mi < 4; mi++)
#pragma unroll
                for (int ni = 0; ni < 4; ni++)
                    asm volatile(
                        "mma.sync.aligned.m16n8k16.row.col.f32.f16.f16.f32 "
                        "{%0,%1,%2,%3},{%4,%5,%6,%7},{%8,%9},{%0,%1,%2,%3};"
                        : "+f"(acc[mi][ni][0]), "+f"(acc[mi][ni][1]),
                          "+f"(acc[mi][ni][2]), "+f"(acc[mi][ni][3])
                        : "r"(af[mi][0]), "r"(af[mi][1]), "r"(af[mi][2]), "r"(af[mi][3]),
                          "r"(bf[ni][0]), "r"(bf[ni][1]));
        }
    }
#undef LOADK

    __half* Dh = (__half*)Dp + (long)z * sD;
    float*  Df = (float*) Dp + (long)z * sD;
#pragma unroll
    for (int mi = 0; mi < 4; mi++) {
        long r0 = gm + wm + mi * 16 + g;
#pragma unroll
        for (int ni = 0; ni < 4; ni++) {
            long c0 = gn + wn + ni * 8 + tg * 2;
            float v0 = acc[mi][ni][0], v1 = acc[mi][ni][1];
            float v2 = acc[mi][ni][2], v3 = acc[mi][ni][3];
            if (do_tanh) {
                v0 = fast_tanh(v0); v1 = fast_tanh(v1);
                v2 = fast_tanh(v2); v3 = fast_tanh(v3);
            }
            if (out_half) {
                *(__half2*)&Dh[r0 * 256 + c0]       = __floats2half2_rn(v0, v1);
                *(__half2*)&Dh[(r0 + 8) * 256 + c0] = __floats2half2_rn(v2, v3);
            } else {
                Df[r0 * 256 + c0]           = v0;
                Df[r0 * 256 + c0 + 1]       = v1;
                Df[(r0 + 8) * 256 + c0]     = v2;
                Df[(r0 + 8) * 256 + c0 + 1] = v3;
            }
        }
    }
}

// ---------------------------------------------------------------------------
// Elementwise / gather / scatter kernels
// ---------------------------------------------------------------------------
__global__ void k_zero4(float4* p, long n4) {
    for (long i = blockIdx.x * (long)blockDim.x + threadIdx.x; i < n4;
         i += (long)gridDim.x * blockDim.x)
        p[i] = make_float4(0.f, 0.f, 0.f, 0.f);
}

// new_nodes -> d_out (fp32) + half copy of compact rows into g_H
__global__ void k_scatter(const float4* __restrict__ x, const float4* __restrict__ nodes,
                          const int* __restrict__ T, float4* __restrict__ out_nn) {
    const long total = (long)cB * cN * 64;
    for (long idx = blockIdx.x * (long)blockDim.x + threadIdx.x; idx < total;
         idx += (long)gridDim.x * blockDim.x) {
        int b   = (int)(idx / (cN * 64));
        int rem = (int)(idx - (long)b * (cN * 64));
        int n = rem >> 6, q = rem & 63;
        int d = n - T[b];
        float4 v = (d >= 0 && d < cT) ? x[((long)b * cT + d) * 64 + q] : nodes[idx];
        out_nn[idx] = v;
        if (n < cNC) {
            __half2* hp = (__half2*)&g_H[((long)b * cNC + n) * cF + q * 4];
            hp[0] = __floats2half2_rn(v.x, v.y);
            hp[1] = __floats2half2_rn(v.z, v.w);
        }
    }
}

// X rows of g_H are exactly x (taus == t, scatter overwrites those rows)
__global__ void k_castx(const float2* __restrict__ x) {
    const long total = (long)MX * cF / 2;
    for (long i = blockIdx.x * (long)blockDim.x + threadIdx.x; i < total;
         i += (long)gridDim.x * blockDim.x) {
        float2 v = x[i];
        *(__half2*)&g_H[(long)M1 * cF + i * 2] = __floats2half2_rn(v.x, v.y);
    }
}

__global__ void k_edges_cast(const int* __restrict__ e, float* __restrict__ o) {
    const int total = cB * 2 * cE;
    for (int i = blockIdx.x * blockDim.x + threadIdx.x; i < total; i += gridDim.x * blockDim.x)
        o[i] = (float)e[i];
}
__global__ void k_copy4(const float4* __restrict__ s, float4* __restrict__ d, int n4) {
    for (int i = blockIdx.x * blockDim.x + threadIdx.x; i < n4; i += gridDim.x * blockDim.x)
        d[i] = s[i];
}
__global__ void k_tt(const int* __restrict__ T, const int* __restrict__ taus, float* __restrict__ o) {
    int i = threadIdx.x;
    if (i < cB) o[i] = (float)(T[i] + taus[i]);
}

__global__ void k_adj_build(const int* __restrict__ edges, const float* __restrict__ w) {
    const int total = cB * cE;
    for (int i = blockIdx.x * blockDim.x + threadIdx.x; i < total; i += gridDim.x * blockDim.x) {
        int b = i / cE, e = i - b * cE;
        int s = edges[(long)b * 2 * cE + e];
        int d = edges[(long)b * 2 * cE + cE + e];
        if (s >= 0 && d >= 0 && s < cNC && d < cNC)
            atomicAdd(&g_adj[((long)b * cNC + d) * cNC + s], w[(long)b * cE + e]);
    }
}

__global__ void k_cvt_adj(const float4* __restrict__ a, long n4) {
    for (long i = blockIdx.x * (long)blockDim.x + threadIdx.x; i < n4;
         i += (long)gridDim.x * blockDim.x) {
        float4 v = a[i];
        __half2* hp = (__half2*)&g_adjh[i * 4];
        hp[0] = __floats2half2_rn(v.x, v.y);
        hp[1] = __floats2half2_rn(v.z, v.w);
    }
}

// per-batch transpose of compact H: g_HT[b][f][s] = g_H[b*256+s][f]
__global__ void k_transpose(void) {
    __shared__ __half t[32][33];
    int b = blockIdx.z;
    int x0 = blockIdx.x * 32, y0 = blockIdx.y * 32;
    int tx = threadIdx.x, ty = threadIdx.y;
#pragma unroll
    for (int i = 0; i < 4; i++)
        t[ty + i * 8][tx] = g_H[((long)b * cNC + y0 + ty + i * 8) * cF + x0 + tx];
    __syncthreads();
#pragma unroll
    for (int i = 0; i < 4; i++)
        g_HT[((long)b * cNC + x0 + ty + i * 8) * cF + y0 + tx] = t[tx][ty + i * 8];
}

// pack weights transposed to half: g_WT[z][n][k] = W_z[k][n]
__global__ void k_packWT(const float* __restrict__ W0, const float* __restrict__ W1,
                         const float* __restrict__ W2, const float* __restrict__ W3) {
    __shared__ float t[32][33];
    const float* Ws[4] = {W0, W1, W2, W3};
    int z = blockIdx.z;
    int x0 = blockIdx.x * 32, y0 = blockIdx.y * 32;
    int tx = threadIdx.x, ty = threadIdx.y;
#pragma unroll
    for (int i = 0; i < 4; i++)
        t[ty + i * 8][tx] = Ws[z][(y0 + ty + i * 8) * cF + x0 + tx];
    __syncthreads();
#pragma unroll
    for (int i = 0; i < 4; i++)
        g_WT[z][(x0 + ty + i * 8) * cF + y0 + tx] = __float2half(t[tx][ty + i * 8]);
}

// layer-2 aggregation rows + gather self rows: one CTA per batch
__global__ __launch_bounds__(256) void k_aggpack(const int* __restrict__ T) {
    __shared__ float adj_sm[cT][cNC];
    const int b = blockIdx.x;
    const int c = threadIdx.x;
    const int Tb = T[b];

#pragma unroll
    for (int r = 0; r < cT; r++) {
        int row = Tb + r;
        adj_sm[r][c] = (row < cNC) ? g_adj[((long)b * cNC + row) * cNC + c] : 0.f;
    }
    __syncthreads();

    float acc[cT];
#pragma unroll
    for (int r = 0; r < cT; r++) acc[r] = 0.f;

    const __half* h1b = g_h1 + (long)b * cNC * cF;
#pragma unroll 4
    for (int s = 0; s < cNC; s++) {
        float v = __half2float(h1b[(long)s * cF + c]);
#pragma unroll
        for (int r = 0; r < cT; r++) acc[r] += adj_sm[r][s] * v;
    }

#pragma unroll
    for (int r = 0; r < cT; r++) {
        int row = Tb + r;
        long j = (long)b * cT + r;
        g_ag2[j * cF + c] = __float2half(acc[r]);
        g_F1[j * cF + c] = (row < cNC) ? g_h1[((long)b * cNC + row) * cF + c]
                                       : g_h1[((long)M1 + j) * cF + c];
    }
}

// ---------------------------------------------------------------------------
// Launcher
// ---------------------------------------------------------------------------
extern "C" void kernel_launch(void* const* d_in, const int* in_sizes, int n_in,
                              void* d_out, int out_size) {
    const float* x       = (const float*)d_in[0];
    const int*   taus    = (const int*)  d_in[1];
    const float* nodes   = (const float*)d_in[2];
    const int*   edges   = (const int*)  d_in[3];
    const float* weights = (const float*)d_in[4];
    const int*   T       = (const int*)  d_in[5];
    const float* Ws1     = (const float*)d_in[6];
    const float* Wm1     = (const float*)d_in[7];
    const float* Ws2     = (const float*)d_in[8];
    const float* Wm2     = (const float*)d_in[9];

    float* out    = (float*)d_out;
    float* out_mx = out + OFF_MX;
    float* out_nn = out + OFF_NN;
    float* out_ed = out + OFF_ED;
    float* out_wt = out + OFF_WT;
    float* out_tt = out + OFF_TT;

    float  *p_adj;
    __half *p_adjh, *p_H, *p_HT, *p_AH, *p_h1, *p_F1, *p_ag2;
    __half (*p_WT)[cF * cF];
    cudaGetSymbolAddress((void**)&p_adj,  g_adj);
    cudaGetSymbolAddress((void**)&p_adjh, g_adjh);
    cudaGetSymbolAddress((void**)&p_H,    g_H);
    cudaGetSymbolAddress((void**)&p_HT,   g_HT);
    cudaGetSymbolAddress((void**)&p_AH,   g_AH);
    cudaGetSymbolAddress((void**)&p_h1,   g_h1);
    cudaGetSymbolAddress((void**)&p_F1,   g_F1);
    cudaGetSymbolAddress((void**)&p_ag2,  g_ag2);
    cudaGetSymbolAddress((void**)&p_WT,   g_WT);

    // zero fp32 adjacency + AH tail rows (X rows have no incoming aggregation)
    k_zero4<<<2048, 256>>>((float4*)p_adj, (long)cB * cNC * cNC / 4);
    k_zero4<<<256, 256>>>((float4*)(p_AH + (long)M1 * cF), (long)MX * cF / 8);

    // passthrough outputs + half staging
    k_scatter<<<4096, 256>>>((const float4*)x, (const float4*)nodes, T, (float4*)out_nn);
    k_castx<<<512, 256>>>((const float2*)x);
    k_edges_cast<<<2048, 256>>>(edges, out_ed);
    k_copy4<<<1024, 256>>>((const float4*)weights, (float4*)out_wt, cB * cE / 4);
    k_tt<<<1, 128>>>(T, taus, out_tt);

    // graph structure
    k_adj_build<<<4096, 256>>>(edges, weights);
    k_cvt_adj<<<2048, 256>>>((const float4*)p_adj, (long)cB * cNC * cNC / 4);
    k_packWT<<<dim3(8, 8, 4), dim3(32, 8)>>>(Ws1, Wm1, Ws2, Wm2);
    k_transpose<<<dim3(8, 8, cB), dim3(32, 8)>>>();

    // G_A: AH = Adj @ H   (batched 128 x [256,256,256])
    hgemm<<<dim3(2, 2, cB), 256>>>(
        p_adjh, (long)cNC * cNC,
        p_HT,   (long)cNC * cF,
        nullptr, nullptr,
        p_AH, (long)cNC * cF,
        1, 1, 0);

    // G_1: h1 = tanh(Hext @ Ws1 + AHext @ Wm1)   (M=34816, N=256, K=256+256)
    hgemm<<<dim3(2, MEXT / 128, 1), 256>>>(
        p_H, 0,
        p_WT[0], 0,
        p_AH, p_WT[1],
        p_h1, 0,
        2, 1, 1);

    // layer-2 aggregation rows + self-row gather
    k_aggpack<<<cB, 256>>>(T);

    // G_2: mx = tanh(F1 @ Ws2 + ag2 @ Wm2)   (M=2048, N=256, K=256+256)
    hgemm<<<dim3(2, MX / 128, 1), 256>>>(
        p_F1, 0,
        p_WT[2], 0,
        p_ag2, p_WT[3],
        out_mx, 0,
        2, 0, 1);
}

// round 3
// speedup vs baseline: 1.6047x; 1.2020x over previous
#include <cuda_runtime.h>
#include <cuda_fp16.h>
#include <math.h>
#include <stdint.h>

// Problem constants (fixed by the dataset)
constexpr int cB  = 128;
constexpr int cT  = 16;
constexpr int cF  = 256;
constexpr int cN  = 1024;
constexpr int cE  = 8192;
constexpr int cNC = 256;               // edge indices live in [0,256)
constexpr int M1   = cB * cNC;         // 32768 compact rows
constexpr int MX   = cB * cT;          // 2048 output rows
constexpr int MEXT = M1 + MX;          // 34816

// Output layout (flattened tuple, float32): mx | new_nodes | edges | weights | T+taus
constexpr long OFF_MX = 0;
constexpr long OFF_NN = (long)cB * cT * cF;
constexpr long OFF_ED = OFF_NN + (long)cB * cN * cF;
constexpr long OFF_WT = OFF_ED + (long)cB * 2 * cE;
constexpr long OFF_TT = OFF_WT + (long)cB * cE;

// Scratch (__device__ globals — no allocation allowed)
__device__ float  g_adj [(long)cB * cNC * cNC];   // fp32 adjacency (atomic build)
__device__ __half g_adjh[(long)cB * cNC * cNC];   // half copy for MMA
__device__ __half g_H  [(long)MEXT * cF];         // [compact nodes | X rows], half
__device__ __half g_HT [(long)cB * cNC * cF];     // per-batch transposed H [feat][node]
__device__ __half g_AH [(long)MEXT * cF];         // Adj@H (tail rows = 0)
__device__ __half g_h1 [(long)MEXT * cF];         // layer-1 hidden
__device__ __half g_F1 [(long)MX * cF];           // gathered h1 rows (layer-2 self term)
__device__ __half g_ag2[(long)MX * cF];           // layer-2 aggregation rows
__device__ __half g_WT [4][cF * cF];              // Ws1^T, Wm1^T, Ws2^T, Wm2^T (half)

// ---------------------------------------------------------------------------
// helpers
// ---------------------------------------------------------------------------
__device__ __forceinline__ void cpa16(void* s, const void* g) {
    unsigned sa = (unsigned)__cvta_generic_to_shared(s);
    asm volatile("cp.async.cg.shared.global [%0], [%1], 16;" :: "r"(sa), "l"(g));
}
__device__ __forceinline__ float fast_tanh(float x) {
    float ax = fabsf(x);
    float e;
    asm("ex2.approx.f32 %0, %1;" : "=f"(e) : "f"(ax * 2.8853900817779268f));
    float t = 1.0f - __fdividef(2.0f, e + 1.0f);
    return copysignf(t, x);
}
#define LDSM4(R, ADDR)                                                          \
    asm volatile("ldmatrix.sync.aligned.m8n8.x4.shared.b16 {%0,%1,%2,%3}, [%4];"\
                 : "=r"((R)[0]), "=r"((R)[1]), "=r"((R)[2]), "=r"((R)[3])       \
                 : "r"(ADDR))

// ---------------------------------------------------------------------------
// fp16 pipelined GEMM: D = [tanh]( A1@B1t [+ A2@B2t] )
// A row-major [M][256] per segment; B TRANSPOSED: [N][256] row-major.
// CTA tile 128x128, K-block 32, cp.async double buffer, ldmatrix + m16n8k16.
// ---------------------------------------------------------------------------
__global__ __launch_bounds__(256, 2) void hgemm(
    const __half* __restrict__ A1, long sA,
    const __half* __restrict__ B1, long sB,
    const __half* __restrict__ A2, const __half* __restrict__ B2,
    void* __restrict__ Dp, long sD,
    int nseg, int out_half, int do_tanh)
{
    __shared__ alignas(16) __half As[2][128 * 40];
    __shared__ alignas(16) __half Bs[2][128 * 40];

    const int z = blockIdx.z;
    const __half* Ab[2]; Ab[0] = A1 + (long)z * sA; Ab[1] = A2 ? A2 + (long)z * sA : Ab[0];
    const __half* Bb[2]; Bb[0] = B1 + (long)z * sB; Bb[1] = B2 ? B2 : Bb[0];

    const long gm = (long)blockIdx.y * 128;
    const long gn = (long)blockIdx.x * 128;
    const int tid = threadIdx.x, warp = tid >> 5, lane = tid & 31;
    const int g = lane >> 2, tg = lane & 3;
    const int wm = (warp & 1) * 64, wn = (warp >> 1) * 32;
    const int nkb = nseg * 8;
    const int lrow = tid >> 1, lcol = (tid & 1) * 16;

    // ldmatrix smem byte offsets
    unsigned aBase[2] = { (unsigned)__cvta_generic_to_shared(As[0]),
                          (unsigned)__cvta_generic_to_shared(As[1]) };
    unsigned bBase[2] = { (unsigned)__cvta_generic_to_shared(Bs[0]),
                          (unsigned)__cvta_generic_to_shared(Bs[1]) };
    int aoff[4], boff[2];
#pragma unroll
    for (int mi = 0; mi < 4; mi++)
        aoff[mi] = ((wm + mi * 16 + (lane & 15)) * 40 + (lane >> 4) * 8) * 2;
    {
        int q = lane >> 3, r = lane & 7;
#pragma unroll
        for (int pi = 0; pi < 2; pi++)
            boff[pi] = ((wn + pi * 16 + (q >> 1) * 8 + r) * 40 + (q & 1) * 8) * 2;
    }

    float acc[4][4][4];
#pragma unroll
    for (int a = 0; a < 4; a++)
#pragma unroll
        for (int b = 0; b < 4; b++)
#pragma unroll
            for (int c = 0; c < 4; c++) acc[a][b][c] = 0.f;

#define LOADK(KB, BUF) do {                                                     \
    int seg_ = (KB) >> 3, kk_ = ((KB) & 7) * 32;                                \
    const __half* Ag_ = Ab[seg_] + (gm + lrow) * 256 + kk_ + lcol;              \
    const __half* Bg_ = Bb[seg_] + (gn + lrow) * 256 + kk_ + lcol;              \
    __half* Asd_ = &As[BUF][lrow * 40 + lcol];                                  \
    __half* Bsd_ = &Bs[BUF][lrow * 40 + lcol];                                  \
    cpa16(Asd_, Ag_); cpa16(Asd_ + 8, Ag_ + 8);                                 \
    cpa16(Bsd_, Bg_); cpa16(Bsd_ + 8, Bg_ + 8);                                 \
    asm volatile("cp.async.commit_group;");                                     \
} while (0)

    LOADK(0, 0);
    for (int kb = 0; kb < nkb; kb++) {
        asm volatile("cp.async.wait_group 0;" ::: "memory");
        __syncthreads();
        if (kb + 1 < nkb) LOADK(kb + 1, (kb + 1) & 1);
        const int buf = kb & 1;

#pragma unroll
        for (int ks = 0; ks < 2; ks++) {
            unsigned af[4][4], bf[2][4];
#pragma unroll
            for (int mi = 0; mi < 4; mi++) LDSM4(af[mi], aBase[buf] + aoff[mi] + ks * 32);
#pragma unroll
            for (int pi = 0; pi < 2; pi++) LDSM4(bf[pi], bBase[buf] + boff[pi] + ks * 32);
#pragma unroll
            for (int mi = 0; mi < 4; mi++)
#pragma unroll
                for (int ni = 0; ni < 4; ni++) {
                    unsigned b0 = bf[ni >> 1][(ni & 1) * 2];
                    unsigned b1 = bf[ni >> 1][(ni & 1) * 2 + 1];
                    asm volatile(
                        "mma.sync.aligned.m16n8k16.row.col.f32.f16.f16.f32 "
                        "{%0,%1,%2,%3},{%4,%5,%6,%7},{%8,%9},{%0,%1,%2,%3};"
                        : "+f"(acc[mi][ni][0]), "+f"(acc[mi][ni][1]),
                          "+f"(acc[mi][ni][2]), "+f"(acc[mi][ni][3])
                        : "r"(af[mi][0]), "r"(af[mi][1]), "r"(af[mi][2]), "r"(af[mi][3]),
                          "r"(b0), "r"(b1));
                }
        }
    }
#undef LOADK

    __half* Dh = (__half*)Dp + (long)z * sD;
    float*  Df = (float*) Dp + (long)z * sD;
#pragma unroll
    for (int mi = 0; mi < 4; mi++) {
        long r0 = gm + wm + mi * 16 + g;
#pragma unroll
        for (int ni = 0; ni < 4; ni++) {
            long c0 = gn + wn + ni * 8 + tg * 2;
            float v0 = acc[mi][ni][0], v1 = acc[mi][ni][1];
            float v2 = acc[mi][ni][2], v3 = acc[mi][ni][3];
            if (do_tanh) {
                v0 = fast_tanh(v0); v1 = fast_tanh(v1);
                v2 = fast_tanh(v2); v3 = fast_tanh(v3);
            }
            if (out_half) {
                *(__half2*)&Dh[r0 * 256 + c0]       = __floats2half2_rn(v0, v1);
                *(__half2*)&Dh[(r0 + 8) * 256 + c0] = __floats2half2_rn(v2, v3);
            } else {
                Df[r0 * 256 + c0]           = v0;
                Df[r0 * 256 + c0 + 1]       = v1;
                Df[(r0 + 8) * 256 + c0]     = v2;
                Df[(r0 + 8) * 256 + c0 + 1] = v3;
            }
        }
    }
}

// ---------------------------------------------------------------------------
// Elementwise / gather / scatter kernels
// ---------------------------------------------------------------------------
__global__ void k_zero4(float4* p, long n4) {
    for (long i = blockIdx.x * (long)blockDim.x + threadIdx.x; i < n4;
         i += (long)gridDim.x * blockDim.x)
        p[i] = make_float4(0.f, 0.f, 0.f, 0.f);
}

// passthrough: new_nodes -> d_out (fp32 only)
__global__ void k_scatter(const float4* __restrict__ x, const float4* __restrict__ nodes,
                          const int* __restrict__ T, float4* __restrict__ out_nn) {
    const long total = (long)cB * cN * 64;
    for (long idx = blockIdx.x * (long)blockDim.x + threadIdx.x; idx < total;
         idx += (long)gridDim.x * blockDim.x) {
        int b   = (int)(idx / (cN * 64));
        int rem = (int)(idx - (long)b * (cN * 64));
        int n = rem >> 6, q = rem & 63;
        int d = n - T[b];
        out_nn[idx] = (d >= 0 && d < cT) ? x[((long)b * cT + d) * 64 + q] : nodes[idx];
    }
}

// build compact H (half) AND its per-batch transpose HT in one pass
__global__ void k_buildH(const float* __restrict__ nodes, const float* __restrict__ x,
                         const int* __restrict__ T) {
    __shared__ __half t[32][33];
    int b = blockIdx.z;
    int x0 = blockIdx.x * 32, y0 = blockIdx.y * 32;   // x0: feat, y0: node
    int tx = threadIdx.x, ty = threadIdx.y;
    int Tb = T[b];
#pragma unroll
    for (int i = 0; i < 4; i++) {
        int n = y0 + ty + i * 8;
        int d = n - Tb;
        float v = (d >= 0 && d < cT) ? x[((long)b * cT + d) * cF + x0 + tx]
                                     : nodes[((long)b * cN + n) * cF + x0 + tx];
        __half h = __float2half(v);
        g_H[((long)b * cNC + n) * cF + x0 + tx] = h;
        t[ty + i * 8][tx] = h;
    }
    __syncthreads();
#pragma unroll
    for (int i = 0; i < 4; i++)
        g_HT[((long)b * cNC + x0 + ty + i * 8) * cF + y0 + tx] = t[tx][ty + i * 8];
}

// X rows of g_H are exactly x (taus == t; scatter overwrites those rows)
__global__ void k_castx(const float2* __restrict__ x) {
    const long total = (long)MX * cF / 2;
    for (long i = blockIdx.x * (long)blockDim.x + threadIdx.x; i < total;
         i += (long)gridDim.x * blockDim.x) {
        float2 v = x[i];
        *(__half2*)&g_H[(long)M1 * cF + i * 2] = __floats2half2_rn(v.x, v.y);
    }
}

__global__ void k_edges_cast(const int* __restrict__ e, float* __restrict__ o) {
    const int total = cB * 2 * cE;
    for (int i = blockIdx.x * blockDim.x + threadIdx.x; i < total; i += gridDim.x * blockDim.x)
        o[i] = (float)e[i];
}
__global__ void k_copy4(const float4* __restrict__ s, float4* __restrict__ d, int n4) {
    for (int i = blockIdx.x * blockDim.x + threadIdx.x; i < n4; i += gridDim.x * blockDim.x)
        d[i] = s[i];
}
__global__ void k_tt(const int* __restrict__ T, const int* __restrict__ taus, float* __restrict__ o) {
    int i = threadIdx.x;
    if (i < cB) o[i] = (float)(T[i] + taus[i]);
}

__global__ void k_adj_build(const int* __restrict__ edges, const float* __restrict__ w) {
    const int total = cB * cE;
    for (int i = blockIdx.x * blockDim.x + threadIdx.x; i < total; i += gridDim.x * blockDim.x) {
        int b = i / cE, e = i - b * cE;
        int s = edges[(long)b * 2 * cE + e];
        int d = edges[(long)b * 2 * cE + cE + e];
        if (s >= 0 && d >= 0 && s < cNC && d < cNC)
            atomicAdd(&g_adj[((long)b * cNC + d) * cNC + s], w[(long)b * cE + e]);
    }
}

__global__ void k_cvt_adj(const float4* __restrict__ a, long n4) {
    for (long i = blockIdx.x * (long)blockDim.x + threadIdx.x; i < n4;
         i += (long)gridDim.x * blockDim.x) {
        float4 v = a[i];
        __half2* hp = (__half2*)&g_adjh[i * 4];
        hp[0] = __floats2half2_rn(v.x, v.y);
        hp[1] = __floats2half2_rn(v.z, v.w);
    }
}

// pack weights transposed to half: g_WT[z][n][k] = W_z[k][n]
__global__ void k_packWT(const float* __restrict__ W0, const float* __restrict__ W1,
                         const float* __restrict__ W2, const float* __restrict__ W3) {
    __shared__ float t[32][33];
    const float* Ws[4] = {W0, W1, W2, W3};
    int z = blockIdx.z;
    int x0 = blockIdx.x * 32, y0 = blockIdx.y * 32;
    int tx = threadIdx.x, ty = threadIdx.y;
#pragma unroll
    for (int i = 0; i < 4; i++)
        t[ty + i * 8][tx] = Ws[z][(y0 + ty + i * 8) * cF + x0 + tx];
    __syncthreads();
#pragma unroll
    for (int i = 0; i < 4; i++)
        g_WT[z][(x0 + ty + i * 8) * cF + y0 + tx] = __float2half(t[tx][ty + i * 8]);
}

// layer-2 aggregation rows + gather self rows: one CTA per batch
__global__ __launch_bounds__(256) void k_aggpack(const int* __restrict__ T) {
    __shared__ float adj_sm[cT][cNC];
    const int b = blockIdx.x;
    const int c = threadIdx.x;
    const int Tb = T[b];

#pragma unroll
    for (int r = 0; r < cT; r++) {
        int row = Tb + r;
        adj_sm[r][c] = (row < cNC) ? g_adj[((long)b * cNC + row) * cNC + c] : 0.f;
    }
    __syncthreads();

    float acc[cT];
#pragma unroll
    for (int r = 0; r < cT; r++) acc[r] = 0.f;

    const __half* h1b = g_h1 + (long)b * cNC * cF;
#pragma unroll 4
    for (int s = 0; s < cNC; s++) {
        float v = __half2float(h1b[(long)s * cF + c]);
#pragma unroll
        for (int r = 0; r < cT; r++) acc[r] += adj_sm[r][s] * v;
    }

#pragma unroll
    for (int r = 0; r < cT; r++) {
        int row = Tb + r;
        long j = (long)b * cT + r;
        g_ag2[j * cF + c] = __float2half(acc[r]);
        g_F1[j * cF + c] = (row < cNC) ? g_h1[((long)b * cNC + row) * cF + c]
                                       : g_h1[((long)M1 + j) * cF + c];
    }
}

// ---------------------------------------------------------------------------
// Launcher (forked capture: side streams overlap passthrough with compute)
// ---------------------------------------------------------------------------
extern "C" void kernel_launch(void* const* d_in, const int* in_sizes, int n_in,
                              void* d_out, int out_size) {
    const float* x       = (const float*)d_in[0];
    const int*   taus    = (const int*)  d_in[1];
    const float* nodes   = (const float*)d_in[2];
    const int*   edges   = (const int*)  d_in[3];
    const float* weights = (const float*)d_in[4];
    const int*   T       = (const int*)  d_in[5];
    const float* Ws1     = (const float*)d_in[6];
    const float* Wm1     = (const float*)d_in[7];
    const float* Ws2     = (const float*)d_in[8];
    const float* Wm2     = (const float*)d_in[9];

    float* out    = (float*)d_out;
    float* out_mx = out + OFF_MX;
    float* out_nn = out + OFF_NN;
    float* out_ed = out + OFF_ED;
    float* out_wt = out + OFF_WT;
    float* out_tt = out + OFF_TT;

    float  *p_adj;
    __half *p_adjh, *p_H, *p_HT, *p_AH, *p_h1, *p_F1, *p_ag2;
    __half (*p_WT)[cF * cF];
    cudaGetSymbolAddress((void**)&p_adj,  g_adj);
    cudaGetSymbolAddress((void**)&p_adjh, g_adjh);
    cudaGetSymbolAddress((void**)&p_H,    g_H);
    cudaGetSymbolAddress((void**)&p_HT,   g_HT);
    cudaGetSymbolAddress((void**)&p_AH,   g_AH);
    cudaGetSymbolAddress((void**)&p_h1,   g_h1);
    cudaGetSymbolAddress((void**)&p_F1,   g_F1);
    cudaGetSymbolAddress((void**)&p_ag2,  g_ag2);
    cudaGetSymbolAddress((void**)&p_WT,   g_WT);

    // one-time resources (created on the eager correctness call, before capture)
    static cudaStream_t s1 = nullptr, s2 = nullptr;
    static cudaEvent_t evF = nullptr, ev1 = nullptr, ev2 = nullptr;
    if (!s1) {
        cudaStreamCreateWithFlags(&s1, cudaStreamNonBlocking);
        cudaStreamCreateWithFlags(&s2, cudaStreamNonBlocking);
        cudaEventCreateWithFlags(&evF, cudaEventDisableTiming);
        cudaEventCreateWithFlags(&ev1, cudaEventDisableTiming);
        cudaEventCreateWithFlags(&ev2, cudaEventDisableTiming);
    }

    // fork
    cudaEventRecord(evF, 0);
    cudaStreamWaitEvent(s1, evF, 0);
    cudaStreamWaitEvent(s2, evF, 0);

    // s1: pure passthrough (memory-bound, fully overlapped with compute chain)
    k_scatter<<<4096, 256, 0, s1>>>((const float4*)x, (const float4*)nodes, T, (float4*)out_nn);
    k_edges_cast<<<2048, 256, 0, s1>>>(edges, out_ed);
    k_copy4<<<1024, 256, 0, s1>>>((const float4*)weights, (float4*)out_wt, cB * cE / 4);
    k_tt<<<1, 128, 0, s1>>>(T, taus, out_tt);
    cudaEventRecord(ev1, s1);

    // s2: H staging (H + HT fused), X rows, packed weights, AH tail zero
    k_buildH<<<dim3(8, 8, cB), dim3(32, 8), 0, s2>>>(nodes, x, T);
    k_castx<<<512, 256, 0, s2>>>((const float2*)x);
    k_packWT<<<dim3(8, 8, 4), dim3(32, 8), 0, s2>>>(Ws1, Wm1, Ws2, Wm2);
    k_zero4<<<256, 256, 0, s2>>>((float4*)(p_AH + (long)M1 * cF), (long)MX * cF / 8);
    cudaEventRecord(ev2, s2);

    // main: adjacency chain
    k_zero4<<<2048, 256>>>((float4*)p_adj, (long)cB * cNC * cNC / 4);
    k_adj_build<<<4096, 256>>>(edges, weights);
    k_cvt_adj<<<2048, 256>>>((const float4*)p_adj, (long)cB * cNC * cNC / 4);
    cudaStreamWaitEvent(0, ev2, 0);

    // G_A: AH = Adj @ H   (batched 128 x [256,256,256])
    hgemm<<<dim3(2, 2, cB), 256>>>(
        p_adjh, (long)cNC * cNC,
        p_HT,   (long)cNC * cF,
        nullptr, nullptr,
        p_AH, (long)cNC * cF,
        1, 1, 0);

    // G_1: h1 = tanh(Hext @ Ws1 + AHext @ Wm1)   (M=34816, N=256, K=512)
    hgemm<<<dim3(2, MEXT / 128, 1), 256>>>(
        p_H, 0,
        p_WT[0], 0,
        p_AH, p_WT[1],
        p_h1, 0,
        2, 1, 1);

    // layer-2 aggregation rows + self-row gather
    k_aggpack<<<cB, 256>>>(T);

    // G_2: mx = tanh(F1 @ Ws2 + ag2 @ Wm2)   (M=2048, N=256, K=512)
    hgemm<<<dim3(2, MX / 128, 1), 256>>>(
        p_F1, 0,
        p_WT[2], 0,
        p_ag2, p_WT[3],
        out_mx, 0,
        2, 0, 1);

    // join passthrough branch
    cudaStreamWaitEvent(0, ev1, 0);
}